// round 17
// baseline (speedup 1.0000x reference)
#include <cuda_runtime.h>
#include <math.h>

#define MAX_N    131072
#define NGRAPH   256
#define MAXSEG   1024
#define NBINS    2048
#define RPT      512
#define CHUNKB   4       // bins per thread (2048/512)

// Scratch (static __device__ arrays — no allocation allowed)
__device__ float d_p[MAX_N];        // x[i] . w_rel
__device__ float d_r[MAX_N];        // x[i].w_root + sum_{edges} p[src]
__device__ float d_score[MAX_N];    // fallback scratch only
__device__ float d_w[MAX_N];        // fallback scratch only
__device__ int   d_starts[NGRAPH + 1];

// software grid barrier state (generation counter: no reset needed)
__device__ unsigned g_bar_count = 0;
__device__ unsigned g_bar_gen   = 0;

__device__ __forceinline__ void grid_sync() {
    __syncthreads();
    if (threadIdx.x == 0) {
        __threadfence();
        unsigned gen = *((volatile unsigned*)&g_bar_gen);
        unsigned arrived = atomicAdd(&g_bar_count, 1u);
        if (arrived == gridDim.x - 1) {
            g_bar_count = 0;
            __threadfence();
            atomicAdd(&g_bar_gen, 1u);
        } else {
            while (*((volatile unsigned*)&g_bar_gen) == gen) { }
        }
        __threadfence();
    }
    __syncthreads();
}

__device__ __forceinline__ unsigned score_key(float s) {
    unsigned u = __float_as_uint(s);
    return (u & 0x80000000u) ? ~u : (u | 0x80000000u);   // monotone
}
__device__ __forceinline__ float key_score(unsigned k) {
    return (k & 0x80000000u) ? __uint_as_float(k & 0x7fffffffu)
                             : __uint_as_float(~k);
}
__device__ __forceinline__ float dot4(float4 a, float4 b) {
    return a.x * b.x + a.y * b.y + a.z * b.z + a.w * b.w;
}

// ---------------------------------------------------------------------------
// Single persistent kernel: dots -> barrier -> scatter -> barrier -> rank+pool
// ---------------------------------------------------------------------------
__global__ void __launch_bounds__(RPT)
k_fused(const float* __restrict__ x,
        const int* __restrict__ ei,
        const int* __restrict__ batch,
        const float* __restrict__ w_rel,
        const float* __restrict__ b_rel,
        const float* __restrict__ w_root,
        float* __restrict__ out,
        int N, int E) {
    __shared__ unsigned hist[NBINS];
    __shared__ float    sw[MAXSEG];
    __shared__ unsigned chsum[RPT];
    __shared__ unsigned suf[RPT];
    __shared__ int s_bin, s_m1, s_ncand;
    __shared__ int      cand_idx[MAXSEG];
    __shared__ unsigned cand_key[MAXSEG];
    __shared__ float ps[32][64];

    int t = threadIdx.x;

    // ======== Phase A: node dots (8 threads/node) + starts detection ========
    {
        const float4* wrv = (const float4*)w_rel;
        const float4* wtv = (const float4*)w_root;
        long long total  = (long long)N * 8;
        long long stride = (long long)gridDim.x * RPT;
        for (long long gid = (long long)blockIdx.x * RPT + t; gid < total; gid += stride) {
            int node = (int)(gid >> 3);
            int sub  = (int)(gid & 7);
            const float4* xr = (const float4*)(x + (size_t)node * 64);
            float4 v0 = xr[sub];
            float4 v1 = xr[sub + 8];
            float a = dot4(v0, wrv[sub]) + dot4(v1, wrv[sub + 8]);
            float b = dot4(v0, wtv[sub]) + dot4(v1, wtv[sub + 8]);
#pragma unroll
            for (int o = 4; o; o >>= 1) {
                a += __shfl_xor_sync(0xffffffffu, a, o);
                b += __shfl_xor_sync(0xffffffffu, b, o);
            }
            if (sub == 0) {
                d_p[node] = a;
                d_r[node] = b;
                int bi = batch[node];
                if (node == 0) {
                    for (int g = 0; g <= bi; ++g) d_starts[g] = 0;
                } else {
                    int bp = batch[node - 1];
                    for (int g = bp + 1; g <= bi; ++g) d_starts[g] = node;
                }
                if (node == N - 1) {
                    for (int g = bi + 1; g <= NGRAPH; ++g) d_starts[g] = N;
                }
            }
        }
    }
    grid_sync();

    // ======== Phase B: edge scatter r[dst] += p[src] (8 edges/thread) =======
    {
        int E8 = E >> 3;
        int stride = gridDim.x * RPT;
        const int4* sv = (const int4*)ei;
        const int4* dv = (const int4*)(ei + E);
        for (int idx = blockIdx.x * RPT + t; idx < E8; idx += stride) {
            int4 sa = __ldcs(&sv[2 * idx]);
            int4 sb = __ldcs(&sv[2 * idx + 1]);
            int4 da = __ldcs(&dv[2 * idx]);
            int4 db = __ldcs(&dv[2 * idx + 1]);
            float p0 = d_p[sa.x], p1 = d_p[sa.y], p2 = d_p[sa.z], p3 = d_p[sa.w];
            float p4 = d_p[sb.x], p5 = d_p[sb.y], p6 = d_p[sb.z], p7 = d_p[sb.w];
            atomicAdd(&d_r[da.x], p0);
            atomicAdd(&d_r[da.y], p1);
            atomicAdd(&d_r[da.z], p2);
            atomicAdd(&d_r[da.w], p3);
            atomicAdd(&d_r[db.x], p4);
            atomicAdd(&d_r[db.y], p5);
            atomicAdd(&d_r[db.z], p6);
            atomicAdd(&d_r[db.w], p7);
        }
        int base = E8 << 3;
        int rem = E - base;
        for (int idx = blockIdx.x * RPT + t; idx < rem; idx += stride) {
            atomicAdd(&d_r[__ldcs(&ei[E + base + idx])], d_p[__ldcs(&ei[base + idx])]);
        }
    }
    grid_sync();

    // ======== Phase C: per-graph score + histogram select + pool ===========
    for (int g = blockIdx.x; g < NGRAPH; g += gridDim.x) {
        if (t == 0) { s_bin = -1; s_m1 = 0; s_ncand = 0; }
#pragma unroll
        for (int b = 0; b < CHUNKB; ++b) hist[t * CHUNKB + b] = 0;

        int start = d_starts[g];
        int end   = d_starts[g + 1];
        int n = end - start;
        int k = (n + 1) >> 1;
        float invk = 1.0f / fmaxf((float)k, 1.0f);
        float bias = b_rel[0];
        __syncthreads();

        if (n <= MAXSEG) {
            for (int i = t; i < n; i += RPT) {
                float sc = tanhf(d_r[start + i] + bias);
                unsigned key = score_key(sc);
                cand_key[i] = key;
                atomicAdd(&hist[key >> 21], 1u);
            }
            __syncthreads();

            unsigned cs = 0;
#pragma unroll
            for (int b = 0; b < CHUNKB; ++b) cs += hist[t * CHUNKB + b];
            chsum[t] = cs;
            __syncthreads();

            if (t < 32) {
                unsigned v[16];
                unsigned tot = 0;
#pragma unroll
                for (int j = 15; j >= 0; --j) {
                    tot += chsum[t * 16 + j];
                    v[j] = tot;
                }
                unsigned run = tot;
#pragma unroll
                for (int off = 1; off < 32; off <<= 1) {
                    unsigned q = __shfl_down_sync(0xffffffffu, run, off);
                    if (t + off < 32) run += q;
                }
                unsigned tail = run - tot;
#pragma unroll
                for (int j = 0; j < 16; ++j) suf[t * 16 + j] = v[j] + tail;
            }
            __syncthreads();

            {
                unsigned above = suf[t] - chsum[t];
                if ((int)above < k && k <= (int)suf[t]) {
                    int acc = (int)above;
                    for (int b = CHUNKB - 1; b >= 0; --b) {
                        int h = (int)hist[t * CHUNKB + b];
                        if (acc < k && k <= acc + h) { s_bin = t * CHUNKB + b; s_m1 = acc; }
                        acc += h;
                    }
                }
            }
            __syncthreads();

            int binb = s_bin, m1 = s_m1;
            for (int i = t; i < n; i += RPT) {
                unsigned key = cand_key[i];
                int bin = (int)(key >> 21);
                if (bin > binb) {
                    sw[i] = key_score(key) * invk;
                } else if (bin < binb) {
                    sw[i] = 0.0f;
                } else {
                    int c = atomicAdd(&s_ncand, 1);
                    cand_idx[c] = i;
                }
            }
            __syncthreads();
            int nc = s_ncand;
            unsigned mykey[2];
            int myidx[2];
            int mycnt = 0;
            for (int c = t; c < nc; c += RPT) {
                myidx[mycnt] = cand_idx[c];
                mykey[mycnt] = cand_key[cand_idx[c]];
                ++mycnt;
            }
            __syncthreads();
            for (int c = t, m = 0; c < nc; c += RPT, ++m) cand_key[c] = mykey[m];
            __syncthreads();

            int r = k - m1;
            for (int c = t, m = 0; c < nc; c += RPT, ++m) {
                unsigned ki = mykey[m];
                int ii = myidx[m];
                int cnt = 0;
                for (int j = 0; j < nc; ++j) {
                    unsigned kj = cand_key[j];
                    cnt += (kj > ki) || (kj == ki && cand_idx[j] < ii);
                }
                sw[ii] = (cnt < r) ? key_score(ki) * invk : 0.0f;
            }
            __syncthreads();

            // pool: dual-row stream
            int q  = t & 15;
            int rg = t >> 4;
            const float4* xv = (const float4*)x;
            float4 acc0 = make_float4(0.f, 0.f, 0.f, 0.f);
            float4 acc1 = make_float4(0.f, 0.f, 0.f, 0.f);
            int i = rg;
#pragma unroll 4
            for (; i + 32 < n; i += 64) {
                float w0 = sw[i];
                float w1 = sw[i + 32];
                float4 v0 = xv[(size_t)(start + i) * 16 + q];
                float4 v1 = xv[(size_t)(start + i + 32) * 16 + q];
                acc0.x += w0 * v0.x; acc0.y += w0 * v0.y;
                acc0.z += w0 * v0.z; acc0.w += w0 * v0.w;
                acc1.x += w1 * v1.x; acc1.y += w1 * v1.y;
                acc1.z += w1 * v1.z; acc1.w += w1 * v1.w;
            }
            if (i < n) {
                float w = sw[i];
                float4 v = xv[(size_t)(start + i) * 16 + q];
                acc0.x += w * v.x; acc0.y += w * v.y;
                acc0.z += w * v.z; acc0.w += w * v.w;
            }
            acc0.x += acc1.x; acc0.y += acc1.y;
            acc0.z += acc1.z; acc0.w += acc1.w;
            ps[rg][q * 4 + 0] = acc0.x;
            ps[rg][q * 4 + 1] = acc0.y;
            ps[rg][q * 4 + 2] = acc0.z;
            ps[rg][q * 4 + 3] = acc0.w;
            __syncthreads();
            if (t < 64) {
                float v = 0.0f;
#pragma unroll
                for (int j = 0; j < 32; ++j) v += ps[j][t];
                out[g * 64 + t] = v;
            }
            __syncthreads();
        } else {
            // improbable fallback: O(n^2) via global scratch
            for (int i = t; i < n; i += RPT)
                d_score[start + i] = tanhf(d_r[start + i] + bias);
            __syncthreads();
            for (int i = t; i < n; i += RPT) {
                float si = d_score[start + i];
                int cnt = 0;
                for (int j = 0; j < i; ++j)     cnt += (d_score[start + j] >= si);
                for (int j = i + 1; j < n; ++j) cnt += (d_score[start + j] >  si);
                d_w[start + i] = (cnt < k) ? si * invk : 0.0f;
            }
            __syncthreads();
            int q  = t & 15;
            int rg = t >> 4;
            const float4* xv = (const float4*)x;
            float4 acc = make_float4(0.f, 0.f, 0.f, 0.f);
            for (int i = rg; i < n; i += 32) {
                float w  = d_w[start + i];
                float4 v = xv[(size_t)(start + i) * 16 + q];
                acc.x += w * v.x; acc.y += w * v.y;
                acc.z += w * v.z; acc.w += w * v.w;
            }
            ps[rg][q * 4 + 0] = acc.x;
            ps[rg][q * 4 + 1] = acc.y;
            ps[rg][q * 4 + 2] = acc.z;
            ps[rg][q * 4 + 3] = acc.w;
            __syncthreads();
            if (t < 64) {
                float v = 0.0f;
#pragma unroll
                for (int j = 0; j < 32; ++j) v += ps[j][t];
                out[g * 64 + t] = v;
            }
            __syncthreads();
        }
    }
}

// ---------------------------------------------------------------------------
extern "C" void kernel_launch(void* const* d_in, const int* in_sizes, int n_in,
                              void* d_out, int out_size) {
    const float* x      = (const float*)d_in[0];
    const int*   ei     = (const int*)d_in[1];
    const int*   batch  = (const int*)d_in[2];
    const float* w_rel  = (const float*)d_in[3];
    const float* b_rel  = (const float*)d_in[4];
    const float* w_root = (const float*)d_in[5];
    float*       out    = (float*)d_out;

    int N = in_sizes[2];
    int E = in_sizes[1] / 2;

    // co-resident grid sizing (deterministic host queries; no stream ops)
    int dev = 0;
    cudaGetDevice(&dev);
    int nsm = 0;
    cudaDeviceGetAttribute(&nsm, cudaDevAttrMultiProcessorCount, dev);
    int maxb = 0;
    cudaOccupancyMaxActiveBlocksPerMultiprocessor(&maxb, k_fused, RPT, 0);
    if (nsm <= 0) nsm = 148;
    if (maxb <= 0) maxb = 1;
    int grid = nsm * maxb;

    k_fused<<<grid, RPT>>>(x, ei, batch, w_rel, b_rel, w_root, out, N, E);
}